// round 7
// baseline (speedup 1.0000x reference)
#include <cuda_runtime.h>

// Single-layer LSTM, T=4096, B=1024, I=H=4, seq-first, zero init state.
// 4 lanes per batch element; 128 blocks x 32 threads -> 1 warp per SM.
//
// R3/R6 design (resubmitted after infra failure):
//  1. Exchange (tanh(c), o-gate) across the 4-lane group instead of h, with
//     shuffles issued the moment each value is produced. The 26-cyc SHFL
//     latency is absorbed by the activation tail of the current step instead
//     of sitting on the serial chain. Partners rebuild h_m = so_m * tc_m.
//  2. Software pipelining: the input projection for step t+1 is computed
//     between the recurrent FMAs and the tanh block of step t, so in-order
//     issue has independent filler inside the MUFU stall shadow.
//  3. h carried across the step boundary in a register (single FMUL shared by
//     the output store and the next step's recurrent FMA).
// Activations: MUFU.TANH; sigmoid rows pre-scaled by 0.5
// (sigmoid(x) = 0.5 + 0.5*tanh(x/2)).

#define TLEN   4096
#define BATCH  1024
#define OUTSTRIDE (BATCH * 4)
#define UNROLL 8

__device__ __forceinline__ float tanhf_a(float x) {
    float y; asm("tanh.approx.f32 %0, %1;" : "=f"(y) : "f"(x)); return y;
}
__device__ __forceinline__ float shfl_bfly(float v, int m) {
    float y;
    asm volatile("shfl.sync.bfly.b32 %0, %1, %2, 0x1f, 0xffffffff;"
                 : "=f"(y) : "f"(v), "r"(m));
    return y;
}

__global__ void __launch_bounds__(32, 1)
lstm_recur(const float* __restrict__ input,
           const float* __restrict__ W_ih,
           const float* __restrict__ W_hh,
           const float* __restrict__ b_ih,
           const float* __restrict__ b_hh,
           float* __restrict__ out)
{
    const int g = blockIdx.x * 32 + threadIdx.x;   // 0..4095
    const int b = g >> 2;                          // batch element
    const int j = g & 3;                           // hidden unit owned by lane

    // Gate q: 0=i, 1=f, 2=g(tanh), 3=o. Row r = q*4 + j of the [16,4] mats.
    // Sigmoid rows (q != 2) pre-scaled by 0.5.
    // whh xor-permuted: value from shfl_xor(_,m) multiplies whh[q][m].
    float wih[4][4], whh[4][4], bias[4];
#pragma unroll
    for (int q = 0; q < 4; ++q) {
        const int r = q * 4 + j;
        const float s = (q == 2) ? 1.0f : 0.5f;
#pragma unroll
        for (int m = 0; m < 4; ++m) {
            wih[q][m] = W_ih[r * 4 + m] * s;
            whh[q][m] = W_hh[r * 4 + (j ^ m)] * s;
        }
        bias[q] = (b_ih[r] + b_hh[r]) * s;
    }

    const float4* __restrict__ xin = reinterpret_cast<const float4*>(input) + b;

    // 8-deep software prefetch (double buffer).
    float4 xbuf[UNROLL], xnxt[UNROLL];
#pragma unroll
    for (int u = 0; u < UNROLL; ++u) xbuf[u] = xin[u * BATCH];

    // Recurrent state. tc = tanh(c), so = o-gate; partners' copies arrive
    // via shuffles issued at the tail of the previous step.
    float c = 0.0f, tc = 0.0f, so = 0.0f, h0 = 0.0f;
    float tc1 = 0.0f, tc2 = 0.0f, tc3 = 0.0f;
    float so1 = 0.0f, so2 = 0.0f, so3 = 0.0f;

    // Projection for step 0 (pre-loop).
    float pacc[4];
    {
        const float x0 = xbuf[0].x, x1 = xbuf[0].y, x2 = xbuf[0].z, x3 = xbuf[0].w;
#pragma unroll
        for (int q = 0; q < 4; ++q) {
            float a  = fmaf(x0, wih[q][0], bias[q]);
            float b2 = x1 * wih[q][1];
            a  = fmaf(x2, wih[q][2], a);
            b2 = fmaf(x3, wih[q][3], b2);
            pacc[q] = a + b2;
        }
    }

    float* op = out + g;

#pragma unroll 1
    for (int t0 = 0; t0 < TLEN; t0 += UNROLL) {
        // Prefetch next block of x (landing ~700 cyc later; off-chain).
#pragma unroll
        for (int u = 0; u < UNROLL; ++u) {
            int tp = t0 + UNROLL + u;
            tp = (tp < TLEN) ? tp : (TLEN - 1);
            xnxt[u] = xin[tp * BATCH];
        }

#pragma unroll
        for (int u = 0; u < UNROLL; ++u) {
            // ---- 1. Rebuild partner hiddens from shuffled (so, tc). ----
            const float h1 = so1 * tc1;
            const float h2 = so2 * tc2;
            const float h3 = so3 * tc3;

            // ---- 2. Recurrent contribution (trees; h0 path first). ----
            float acc[4];
#pragma unroll
            for (int q = 0; q < 4; ++q) {
                float a  = fmaf(h0, whh[q][0], pacc[q]);
                a  = fmaf(h1, whh[q][1], a);
                float b2 = h2 * whh[q][2];
                b2 = fmaf(h3, whh[q][3], b2);
                acc[q] = a + b2;
            }

            // ---- 3. Filler in the MUFU shadow: projection for step t+1. ----
            {
                const int un = (u + 1) & (UNROLL - 1);
                const float4 xv = (u + 1 < UNROLL) ? xbuf[un] : xnxt[0];
                const float x0 = xv.x, x1 = xv.y, x2 = xv.z, x3 = xv.w;
#pragma unroll
                for (int q = 0; q < 4; ++q) {
                    float a  = fmaf(x0, wih[q][0], bias[q]);
                    float b2 = x1 * wih[q][1];
                    a  = fmaf(x2, wih[q][2], a);
                    b2 = fmaf(x3, wih[q][3], b2);
                    pacc[q] = a + b2;
                }
            }

            // ---- 4. Activations (MUFU.TANH). i,g,f feed the c-path first. ----
            const float ti = tanhf_a(acc[0]);
            const float tg = tanhf_a(acc[2]);
            const float tf = tanhf_a(acc[1]);
            const float to = tanhf_a(acc[3]);

            const float si = fmaf(ti, 0.5f, 0.5f);
            const float sf = fmaf(tf, 0.5f, 0.5f);
            so = fmaf(to, 0.5f, 0.5f);

            // o-gate shuffles: issued early, consumed next step.
            so1 = shfl_bfly(so, 1);
            so2 = shfl_bfly(so, 2);
            so3 = shfl_bfly(so, 3);

            // ---- 5. Cell update and h output. ----
            c  = fmaf(si, tg, sf * c);
            tc = tanhf_a(c);

            // tc shuffles: in flight across the step boundary.
            tc1 = shfl_bfly(tc, 1);
            tc2 = shfl_bfly(tc, 2);
            tc3 = shfl_bfly(tc, 3);

            h0 = so * tc;                       // h(t): store + next-step reuse
            op[(t0 + u) * OUTSTRIDE] = h0;      // coalesced
        }

#pragma unroll
        for (int u = 0; u < UNROLL; ++u) xbuf[u] = xnxt[u];
    }
}

extern "C" void kernel_launch(void* const* d_in, const int* in_sizes, int n_in,
                              void* d_out, int out_size)
{
    const float* input = (const float*)d_in[0];
    const float* W_ih  = (const float*)d_in[1];
    const float* W_hh  = (const float*)d_in[2];
    const float* b_ih  = (const float*)d_in[3];
    const float* b_hh  = (const float*)d_in[4];
    float* out = (float*)d_out;

    lstm_recur<<<128, 32>>>(input, W_ih, W_hh, b_ih, b_hh, out);
}

// round 9
// speedup vs baseline: 1.0529x; 1.0529x over previous
#include <cuda_runtime.h>

// Single-layer LSTM, T=4096, B=1024, I=H=4, seq-first, zero init state.
// 4 lanes per batch element; 128 blocks x 32 threads -> 1 warp per SM.
//
// R7: R2 structure (fastest so far: shfl h after producing it, inline proj)
// with all gate arithmetic in packed f32x2 (SASS FFMA2, 2 FMAs/issue slot).
// Gate accumulators packed as (i,f) and (g,o); the 0.5 sigmoid pre-scale
// (sigmoid(x) = 0.5 + 0.5*tanh(x/2)) is folded per-component into the packed
// weights/bias. This halves the FFMA issue pressure under the serial chain
// (static ~65 -> ~44 instrs/step, fma-pipe load ~90 -> ~50 cyc).
// Activations: MUFU.TANH.

#define TLEN   4096
#define BATCH  1024
#define OUTSTRIDE (BATCH * 4)
#define UNROLL 8

typedef unsigned long long u64;

__device__ __forceinline__ float tanhf_a(float x) {
    float y; asm("tanh.approx.f32 %0, %1;" : "=f"(y) : "f"(x)); return y;
}
__device__ __forceinline__ u64 pack2(float lo, float hi) {
    u64 r; asm("mov.b64 %0, {%1, %2};" : "=l"(r) : "f"(lo), "f"(hi)); return r;
}
__device__ __forceinline__ void unpack2(float& lo, float& hi, u64 v) {
    asm("mov.b64 {%0, %1}, %2;" : "=f"(lo), "=f"(hi) : "l"(v));
}
__device__ __forceinline__ u64 fma2(u64 a, u64 b, u64 c) {
    u64 r; asm("fma.rn.f32x2 %0, %1, %2, %3;" : "=l"(r) : "l"(a), "l"(b), "l"(c)); return r;
}
__device__ __forceinline__ u64 mul2(u64 a, u64 b) {
    u64 r; asm("mul.rn.f32x2 %0, %1, %2;" : "=l"(r) : "l"(a), "l"(b)); return r;
}
__device__ __forceinline__ u64 add2(u64 a, u64 b) {
    u64 r; asm("add.rn.f32x2 %0, %1, %2;" : "=l"(r) : "l"(a), "l"(b)); return r;
}
__device__ __forceinline__ float shfl_bfly(float v, int m) {
    float y;
    asm volatile("shfl.sync.bfly.b32 %0, %1, %2, 0x1f, 0xffffffff;"
                 : "=f"(y) : "f"(v), "r"(m));
    return y;
}

__global__ void __launch_bounds__(32, 1)
lstm_recur(const float* __restrict__ input,
           const float* __restrict__ W_ih,
           const float* __restrict__ W_hh,
           const float* __restrict__ b_ih,
           const float* __restrict__ b_hh,
           float* __restrict__ out)
{
    const int g = blockIdx.x * 32 + threadIdx.x;   // 0..4095
    const int b = g >> 2;                          // batch element
    const int j = g & 3;                           // hidden unit owned by lane

    // PyTorch gate rows for unit j: i=j, f=4+j, g=8+j, o=12+j.
    // Pack A = (i, f) both pre-scaled 0.5; pack B = (g, o) scaled (1.0, 0.5).
    // W_hh columns xor-permuted: shfl_xor(h, m) multiplies column (j^m).
    const int ri = j, rf = 4 + j, rg = 8 + j, ro = 12 + j;
    u64 wA[4], wB[4], uA[4], uB[4];
#pragma unroll
    for (int m = 0; m < 4; ++m) {
        wA[m] = pack2(W_ih[ri * 4 + m] * 0.5f, W_ih[rf * 4 + m] * 0.5f);
        wB[m] = pack2(W_ih[rg * 4 + m],        W_ih[ro * 4 + m] * 0.5f);
        const int mc = j ^ m;
        uA[m] = pack2(W_hh[ri * 4 + mc] * 0.5f, W_hh[rf * 4 + mc] * 0.5f);
        uB[m] = pack2(W_hh[rg * 4 + mc],        W_hh[ro * 4 + mc] * 0.5f);
    }
    const u64 biasA = pack2((b_ih[ri] + b_hh[ri]) * 0.5f,
                            (b_ih[rf] + b_hh[rf]) * 0.5f);
    const u64 biasB = pack2((b_ih[rg] + b_hh[rg]),
                            (b_ih[ro] + b_hh[ro]) * 0.5f);

    const float4* __restrict__ xin = reinterpret_cast<const float4*>(input) + b;

    // 8-deep software prefetch (double buffer): covers 577-cyc DRAM latency.
    float4 xbuf[UNROLL], xnxt[UNROLL];
#pragma unroll
    for (int u = 0; u < UNROLL; ++u) xbuf[u] = xin[u * BATCH];

    float h = 0.0f, c = 0.0f;
    float* op = out + g;

#pragma unroll 1
    for (int t0 = 0; t0 < TLEN; t0 += UNROLL) {
#pragma unroll
        for (int u = 0; u < UNROLL; ++u) {
            int tp = t0 + UNROLL + u;
            tp = (tp < TLEN) ? tp : (TLEN - 1);
            xnxt[u] = xin[tp * BATCH];
        }

#pragma unroll
        for (int u = 0; u < UNROLL; ++u) {
            // ---- Input projection, packed (off the serial chain). ----
            const u64 x0p = pack2(xbuf[u].x, xbuf[u].x);
            const u64 x1p = pack2(xbuf[u].y, xbuf[u].y);
            const u64 x2p = pack2(xbuf[u].z, xbuf[u].z);
            const u64 x3p = pack2(xbuf[u].w, xbuf[u].w);

            u64 pA = fma2(x0p, wA[0], biasA);
            u64 pB = fma2(x0p, wB[0], biasB);
            pA = fma2(x1p, wA[1], pA);
            pB = fma2(x1p, wB[1], pB);
            pA = fma2(x2p, wA[2], pA);
            pB = fma2(x2p, wB[2], pB);
            pA = fma2(x3p, wA[3], pA);
            pB = fma2(x3p, wB[3], pB);

            // ---- Exchange hidden state (3 shfls; h from previous step). ----
            const float h1 = shfl_bfly(h, 1);
            const float h2 = shfl_bfly(h, 2);
            const float h3 = shfl_bfly(h, 3);

            const u64 h0p = pack2(h, h);          // starts before shfls land
            u64 aA = fma2(h0p, uA[0], pA);
            u64 aB = fma2(h0p, uB[0], pB);

            const u64 h1p = pack2(h1, h1);
            const u64 h2p = pack2(h2, h2);
            const u64 h3p = pack2(h3, h3);
            aA = fma2(h1p, uA[1], aA);
            aB = fma2(h1p, uB[1], aB);
            u64 tA = mul2(h2p, uA[2]);
            u64 tB = mul2(h2p, uB[2]);
            tA = fma2(h3p, uA[3], tA);
            tB = fma2(h3p, uB[3], tB);
            aA = add2(aA, tA);
            aB = add2(aB, tB);

            // ---- Activations (MUFU.TANH); f first (c-path), o last. ----
            float ai, af, ag, ao;
            unpack2(ai, af, aA);
            unpack2(ag, ao, aB);

            const float tf = tanhf_a(af);
            const float ti = tanhf_a(ai);
            const float tg = tanhf_a(ag);
            const float to = tanhf_a(ao);

            const float sf = fmaf(tf, 0.5f, 0.5f);
            const float si = fmaf(ti, 0.5f, 0.5f);
            const float so = fmaf(to, 0.5f, 0.5f);

            // ---- Cell update and h output. ----
            c = fmaf(si, tg, sf * c);
            const float tc = tanhf_a(c);
            h = so * tc;

            op[(t0 + u) * OUTSTRIDE] = h;        // coalesced
        }

#pragma unroll
        for (int u = 0; u < UNROLL; ++u) xbuf[u] = xnxt[u];
    }
}

extern "C" void kernel_launch(void* const* d_in, const int* in_sizes, int n_in,
                              void* d_out, int out_size)
{
    const float* input = (const float*)d_in[0];
    const float* W_ih  = (const float*)d_in[1];
    const float* W_hh  = (const float*)d_in[2];
    const float* b_ih  = (const float*)d_in[3];
    const float* b_hh  = (const float*)d_in[4];
    float* out = (float*)d_out;

    lstm_recur<<<128, 32>>>(input, W_ih, W_hh, b_ih, b_hh, out);
}